// round 13
// baseline (speedup 1.0000x reference)
#include <cuda_runtime.h>
#include <math.h>

#define HIDDEN 2048
#define INPUT_D 128
#define BATCH 2048
#define FIVEH (5 * HIDDEN)

// Scratch for up = input @ W^T + b  (2048 x 10240 f32 = 84MB)
__device__ __align__(16) float g_up[(size_t)BATCH * FIVEH];

__device__ __forceinline__ long long ll_min2(long long a, long long b) {
    return a < b ? a : b;
}

// ============================================================================
// Kernel 1: SGEMM  C[m,n] = sum_k A[m,k] * W[n,k] + bias[n]
// ============================================================================
#define BM 128
#define BN 128
#define BK 16

__global__ __launch_bounds__(256) void gemm_kernel(
    const float* __restrict__ A,
    const float* __restrict__ W,
    const float* __restrict__ bias,
    long long aLim, long long wLim, long long bLim)
{
    __shared__ float As[BK][BM];
    __shared__ float Ws[BK][BN];

    const int tid = threadIdx.x;
    const int bn = blockIdx.x * BN;
    const int bm = blockIdx.y * BM;
    const int tx = tid & 15;
    const int ty = tid >> 4;

    const long long aLast = (aLim & ~3LL) - 4;
    const long long wLast = (wLim & ~3LL) - 4;
    const long long bLast = bLim - 1;

    float acc[8][8];
#pragma unroll
    for (int i = 0; i < 8; i++)
#pragma unroll
        for (int j = 0; j < 8; j++) acc[i][j] = 0.0f;

    for (int k0 = 0; k0 < INPUT_D; k0 += BK) {
#pragma unroll
        for (int q = 0; q < 2; q++) {
            int slot = tid + q * 256;
            int m = slot >> 2;
            int k4 = (slot & 3) << 2;
            long long aoff = ll_min2((long long)(bm + m) * INPUT_D + k0 + k4, aLast);
            float4 va = *(const float4*)(A + aoff);
            As[k4 + 0][m] = va.x; As[k4 + 1][m] = va.y;
            As[k4 + 2][m] = va.z; As[k4 + 3][m] = va.w;
            long long woff = ll_min2((long long)(bn + m) * INPUT_D + k0 + k4, wLast);
            float4 vw = *(const float4*)(W + woff);
            Ws[k4 + 0][m] = vw.x; Ws[k4 + 1][m] = vw.y;
            Ws[k4 + 2][m] = vw.z; Ws[k4 + 3][m] = vw.w;
        }
        __syncthreads();

#pragma unroll
        for (int k = 0; k < BK; k++) {
            float a[8], w[8];
            *(float4*)(a)     = *(const float4*)&As[k][ty * 8];
            *(float4*)(a + 4) = *(const float4*)&As[k][ty * 8 + 4];
            *(float4*)(w)     = *(const float4*)&Ws[k][tx * 8];
            *(float4*)(w + 4) = *(const float4*)&Ws[k][tx * 8 + 4];
#pragma unroll
            for (int i = 0; i < 8; i++)
#pragma unroll
                for (int j = 0; j < 8; j++)
                    acc[i][j] = fmaf(a[i], w[j], acc[i][j]);
        }
        __syncthreads();
    }

#pragma unroll
    for (int i = 0; i < 8; i++) {
        int m = bm + ty * 8 + i;
        float* crow = g_up + (size_t)m * FIVEH + bn + tx * 8;
#pragma unroll
        for (int j = 0; j < 8; j += 4) {
            long long n = bn + tx * 8 + j;
            float4 v;
            v.x = acc[i][j + 0] + bias[ll_min2(n + 0, bLast)];
            v.y = acc[i][j + 1] + bias[ll_min2(n + 1, bLast)];
            v.z = acc[i][j + 2] + bias[ll_min2(n + 2, bLast)];
            v.w = acc[i][j + 3] + bias[ll_min2(n + 3, bLast)];
            *(float4*)(crow + j) = v;
        }
    }
}

// ============================================================================
// Kernel 2: fused URNN core. One block per batch row.
// ============================================================================

__device__ __forceinline__ float2 cmul(float2 a, float2 b) {
    return make_float2(a.x * b.x - a.y * b.y, a.x * b.y + a.y * b.x);
}

template <int SIGN>
__device__ float2* fft2048(float2* __restrict__ a, float2* __restrict__ b, int tid)
{
    float2* src = a;
    float2* dst = b;
    int m = 1;
    const float CTW = SIGN * 3.14159265358979f / 1024.0f;

#pragma unroll 1
    for (int st = 0; st < 11; st++) {
#pragma unroll
        for (int q = 0; q < 4; q++) {
            int idx = tid + q * 256;
            int k = idx & (m - 1);
            float2 c0 = src[idx];
            float2 c1 = src[idx + 1024];
            float2 sum = make_float2(c0.x + c1.x, c0.y + c1.y);
            float2 dif = make_float2(c0.x - c1.x, c0.y - c1.y);
            float ang = (float)(idx - k) * CTW;
            float sw, cw;
            __sincosf(ang, &sw, &cw);
            float2 t = make_float2(cw * dif.x - sw * dif.y,
                                   cw * dif.y + sw * dif.x);
            int d0 = (idx << 1) - k;
            dst[d0] = sum;
            dst[d0 + m] = t;
        }
        __syncthreads();
        float2* tmp = src; src = dst; dst = tmp;
        m <<= 1;
    }
    return src;
}

__device__ __forceinline__ float2 block_reduce_c2(float2 v, float2* red)
{
#pragma unroll
    for (int off = 16; off > 0; off >>= 1) {
        v.x += __shfl_xor_sync(0xFFFFFFFFu, v.x, off);
        v.y += __shfl_xor_sync(0xFFFFFFFFu, v.y, off);
    }
    __syncthreads();
    int lane = threadIdx.x & 31;
    int w = threadIdx.x >> 5;
    if (lane == 0) red[w] = v;
    __syncthreads();
    float2 sum = make_float2(0.f, 0.f);
#pragma unroll
    for (int i = 0; i < 8; i++) { sum.x += red[i].x; sum.y += red[i].y; }
    return sum;
}

__global__ __launch_bounds__(256) void fused_kernel(
    const float* __restrict__ hxr,
    const float* __restrict__ hxi,
    const int*   __restrict__ perm,
    const float* __restrict__ beta,
    float*       __restrict__ out,
    long long hxLim,
    long long outCap)                       // writable float count of out
{
    __shared__ float2 bufA[HIDDEN];
    __shared__ float2 bufB[HIDDEN];
    __shared__ float2 red[8];

    const int b = blockIdx.x;
    const int tid = threadIdx.x;
    const float* uprow = g_up + (size_t)b * FIVEH;
    const size_t rowoff = (size_t)b * HIDDEN;
    const long long hxLast = hxLim - 1;

    // ---- load: bufA[i] = d1[i] * hx[i] ----
#pragma unroll
    for (int q = 0; q < 8; q++) {
        int i = tid + q * 256;
        float sp, cp;
        __sincosf(uprow[i], &sp, &cp);                 // d1 = (cp, sp)
        long long hidx = ll_min2((long long)(rowoff + i), hxLast);
        float xr = hxr[hidx];
        float xi = hxi[hidx];
        bufA[i] = make_float2(cp * xr - sp * xi, cp * xi + sp * xr);
    }
    __syncthreads();

    // ---- forward FFT ----
    float2* h = fft2048<-1>(bufA, bufB, tid);

    // ---- householder with r1 (plane 3) ----
    float2 rc[8];
    float2 acc = make_float2(0.f, 0.f);
#pragma unroll
    for (int q = 0; q < 8; q++) {
        int i = tid + q * 256;
        float sp, cp;
        __sincosf(uprow[3 * HIDDEN + i], &sp, &cp);
        rc[q] = make_float2(cp, sp);
        float2 hv = h[i];
        acc.x += cp * hv.x + sp * hv.y;
        acc.y += cp * hv.y - sp * hv.x;
    }
    float2 proj = block_reduce_c2(acc, red);
#pragma unroll
    for (int q = 0; q < 8; q++) {
        int i = tid + q * 256;
        float2 rp = cmul(rc[q], proj);
        float2 hv = h[i];
        h[i] = make_float2(hv.x - 2.f * rp.x, hv.y - 2.f * rp.y);
    }
    __syncthreads();

    // ---- gather permutation + d2 (plane 1) ----
    float2* g = (h == bufA) ? bufB : bufA;
#pragma unroll
    for (int q = 0; q < 8; q++) {
        int i = tid + q * 256;
        float sp, cp;
        __sincosf(uprow[HIDDEN + i], &sp, &cp);        // d2
        float2 hv = h[perm[i] & (HIDDEN - 1)];
        g[i] = make_float2(cp * hv.x - sp * hv.y, cp * hv.y + sp * hv.x);
    }
    __syncthreads();

    // ---- inverse FFT (unnormalized; 1/N folded in later) ----
    float2* h2 = fft2048<1>(g, h, tid);

    // ---- householder with r2 (plane 4) ----
    acc = make_float2(0.f, 0.f);
#pragma unroll
    for (int q = 0; q < 8; q++) {
        int i = tid + q * 256;
        float sp, cp;
        __sincosf(uprow[4 * HIDDEN + i], &sp, &cp);
        rc[q] = make_float2(cp, sp);
        float2 hv = h2[i];
        acc.x += cp * hv.x + sp * hv.y;
        acc.y += cp * hv.y - sp * hv.x;
    }
    float2 proj2 = block_reduce_c2(acc, red);

    const float inv = 1.0f / (float)HIDDEN;
#pragma unroll
    for (int q = 0; q < 8; q++) {
        int i = tid + q * 256;
        float2 rp = cmul(rc[q], proj2);
        float2 hv = h2[i];
        float2 v = make_float2(hv.x - 2.f * rp.x, hv.y - 2.f * rp.y);
        // d3 (plane 2) * v * (1/N)
        float sp, cp;
        __sincosf(uprow[2 * HIDDEN + i], &sp, &cp);
        float2 w = make_float2((cp * v.x - sp * v.y) * inv,
                               (cp * v.y + sp * v.x) * inv);
        // ModReLU
        float mag = sqrtf(w.x * w.x + w.y * w.y);
        float nm = fmaxf(mag + beta[i], 0.0f);
        float2 o;
        if (mag > 0.0f) {
            float sc = nm / mag;
            o = make_float2(w.x * sc, w.y * sc);
        } else {
            o = make_float2(nm, 0.0f);
        }

        // ---- output: adaptive layout based on buffer capacity ----
        long long fidx = (long long)(rowoff + i);
        if (outCap >= 2LL * BATCH * HIDDEN) {
            // buffer holds full complex view -> interleaved (re, im)
            *(float2*)(out + 2 * fidx) = o;
        } else if (fidx < outCap) {
            // buffer holds one float per element -> REAL PART (astype(f32))
            out[fidx] = o.x;
        }
    }
}

// Diagnostic fallback: zero out_size floats (guarded).
__global__ void zero_out_kernel(float* out, long long n)
{
    long long i = (long long)blockIdx.x * blockDim.x + threadIdx.x;
    if (i < n) out[i] = 0.0f;
}

// ============================================================================
// Host: bind inputs BY SIZE (element or byte counts); alphabetical fallback.
// ============================================================================
static inline bool sz_match(long long s, long long elems) {
    return s == elems || s == elems * 4;
}

extern "C" void kernel_launch(void* const* d_in, const int* in_sizes, int n_in,
                              void* d_out, int out_size)
{
    const float* input = nullptr;
    const float* W     = nullptr;
    const float* bias  = nullptr;
    const float* beta  = nullptr;
    const int*   perm  = nullptr;
    const float* hx_first = nullptr;
    const float* hx_second = nullptr;

    long long aLim = (long long)BATCH * INPUT_D;
    long long wLim = (long long)FIVEH * INPUT_D;
    long long bLim = FIVEH;
    long long hxLim = (long long)BATCH * HIDDEN;

    int idx_input = -1, idx_hx_first = -1;

    for (int i = 0; i < n_in; i++) {
        long long s = (long long)in_sizes[i];
        if (sz_match(s, (long long)BATCH * INPUT_D)) {          // 262144
            input = (const float*)d_in[i]; idx_input = i;
        } else if (sz_match(s, (long long)FIVEH * INPUT_D)) {   // 1310720
            W = (const float*)d_in[i];
        } else if (sz_match(s, (long long)FIVEH)) {             // 10240
            bias = (const float*)d_in[i];
        } else if (sz_match(s, (long long)BATCH * HIDDEN)) {    // 4194304
            if (!hx_first) { hx_first = (const float*)d_in[i]; idx_hx_first = i; }
            else           { hx_second = (const float*)d_in[i]; }
        } else if (sz_match(s, (long long)HIDDEN)) {            // 2048
            if (!beta) beta = (const float*)d_in[i];
            else       perm = (const int*)d_in[i];
        }
    }

    const float* hxr = nullptr;
    const float* hxi = nullptr;
    if (hx_first && hx_second) {
        // declared dict order: input precedes hx pair -> real first.
        // alphabetical order:  hx_imag, hx_real precede input -> imag first.
        if (idx_input >= 0 && idx_input < idx_hx_first) {
            hxr = hx_first;  hxi = hx_second;
        } else {
            hxi = hx_first;  hxr = hx_second;
        }
    }

    bool ok = input && W && bias && beta && perm && hxr && hxi;

    if (!ok && n_in == 7) {
        // Fallback: alphabetical key order.
        W     = (const float*)d_in[0];
        bias  = (const float*)d_in[1];
        beta  = (const float*)d_in[2];
        hxi   = (const float*)d_in[3];
        hxr   = (const float*)d_in[4];
        input = (const float*)d_in[5];
        perm  = (const int*)d_in[6];
        aLim  = (long long)in_sizes[5] < aLim  ? (long long)in_sizes[5] : aLim;
        wLim  = (long long)in_sizes[0] < wLim  ? (long long)in_sizes[0] : wLim;
        bLim  = (long long)in_sizes[1] < bLim  ? (long long)in_sizes[1] : bLim;
        long long h3 = (long long)in_sizes[3], h4 = (long long)in_sizes[4];
        long long hmin = h3 < h4 ? h3 : h4;
        hxLim = hmin < hxLim ? hmin : hxLim;
        ok = true;
    }

    long long outCap = (long long)out_size;   // floats we may safely write

    if (!ok) {
        long long n = outCap;
        if (n > 0)
            zero_out_kernel<<<(unsigned)((n + 255) / 256), 256>>>((float*)d_out, n);
        return;
    }

    dim3 g1(FIVEH / BN, BATCH / BM);   // (80, 16)
    gemm_kernel<<<g1, 256>>>(input, W, bias, aLim, wLim, bLim);

    fused_kernel<<<BATCH, 256>>>(hxr, hxi, perm, beta, (float*)d_out,
                                 hxLim, outCap);
}

// round 14
// speedup vs baseline: 1.1704x; 1.1704x over previous
#include <cuda_runtime.h>
#include <math.h>

#define HIDDEN 2048
#define INPUT_D 128
#define BATCH 2048
#define FIVEH (5 * HIDDEN)

// Scratch for up = input @ W^T + b  (2048 x 10240 f32 = 84MB)
__device__ __align__(16) float g_up[(size_t)BATCH * FIVEH];

__device__ __forceinline__ long long ll_min2(long long a, long long b) {
    return a < b ? a : b;
}

// ---- packed f32x2 helpers (Blackwell FFMA2 path, PTX-only) ----
__device__ __forceinline__ unsigned long long pack_dup(float x) {
    unsigned long long r;
    unsigned int u = __float_as_uint(x);
    asm("mov.b64 %0, {%1, %1};" : "=l"(r) : "r"(u));
    return r;
}
__device__ __forceinline__ void fma2(unsigned long long& acc,
                                     unsigned long long a,
                                     unsigned long long b) {
    asm("fma.rn.f32x2 %0, %1, %2, %0;" : "+l"(acc) : "l"(a), "l"(b));
}

// ============================================================================
// Kernel 1: SGEMM  C[m,n] = sum_k A[m,k] * W[n,k] + bias[n]
//   FFMA2 (f32x2) inner loop: 2 FMAs/lane/instr -> 2x the FFMA-3reg issue
//   roofline. Thread tile 16m x 4n; m-pairs come packed straight from LDS.
// ============================================================================
#define BM 128
#define BN 128
#define BK 16

__global__ __launch_bounds__(256) void gemm_kernel(
    const float* __restrict__ A,
    const float* __restrict__ W,
    const float* __restrict__ bias,
    long long aLim, long long wLim, long long bLim)
{
    __shared__ float As[BK][BM];   // [k][m]  (m contiguous)
    __shared__ float Ws[BK][BN];   // [k][n]  (n contiguous)

    const int tid = threadIdx.x;
    const int bn = blockIdx.x * BN;
    const int bm = blockIdx.y * BM;
    const int tx = tid & 31;       // n direction: 32 threads x 4 cols
    const int ty = tid >> 5;       // m direction: 8 threads x 16 rows

    const long long aLast = (aLim & ~3LL) - 4;
    const long long wLast = (wLim & ~3LL) - 4;
    const long long bLast = bLim - 1;

    // acc2[ii][j]: m-pair (2ii, 2ii+1), n = tx*4 + j ; packed f32x2
    unsigned long long acc2[8][4];
#pragma unroll
    for (int i = 0; i < 8; i++)
#pragma unroll
        for (int j = 0; j < 4; j++) acc2[i][j] = 0ull;

    for (int k0 = 0; k0 < INPUT_D; k0 += BK) {
#pragma unroll
        for (int q = 0; q < 2; q++) {
            int slot = tid + q * 256;        // 0..511 float4 slots
            int m = slot >> 2;
            int k4 = (slot & 3) << 2;
            long long aoff = ll_min2((long long)(bm + m) * INPUT_D + k0 + k4, aLast);
            float4 va = *(const float4*)(A + aoff);
            As[k4 + 0][m] = va.x; As[k4 + 1][m] = va.y;
            As[k4 + 2][m] = va.z; As[k4 + 3][m] = va.w;
            long long woff = ll_min2((long long)(bn + m) * INPUT_D + k0 + k4, wLast);
            float4 vw = *(const float4*)(W + woff);
            Ws[k4 + 0][m] = vw.x; Ws[k4 + 1][m] = vw.y;
            Ws[k4 + 2][m] = vw.z; Ws[k4 + 3][m] = vw.w;
        }
        __syncthreads();

#pragma unroll
        for (int k = 0; k < BK; k++) {
            // 16 m values as 8 packed pairs (64B, broadcast across tx)
            unsigned long long a2[8];
            const unsigned long long* ap =
                (const unsigned long long*)&As[k][ty * 16];
#pragma unroll
            for (int ii = 0; ii < 8; ii++) a2[ii] = ap[ii];

            // 4 n values, each duplicated into both f32x2 lanes
            float4 wv = *(const float4*)&Ws[k][tx * 4];
            unsigned long long w2[4];
            w2[0] = pack_dup(wv.x); w2[1] = pack_dup(wv.y);
            w2[2] = pack_dup(wv.z); w2[3] = pack_dup(wv.w);

#pragma unroll
            for (int ii = 0; ii < 8; ii++)
#pragma unroll
                for (int j = 0; j < 4; j++)
                    fma2(acc2[ii][j], a2[ii], w2[j]);
        }
        __syncthreads();
    }

    // Epilogue: unpack pairs, add bias, coalesced float4 stores.
    long long nbase = bn + tx * 4;
    float4 bv;
    bv.x = bias[ll_min2(nbase + 0, bLast)];
    bv.y = bias[ll_min2(nbase + 1, bLast)];
    bv.z = bias[ll_min2(nbase + 2, bLast)];
    bv.w = bias[ll_min2(nbase + 3, bLast)];

#pragma unroll
    for (int ii = 0; ii < 8; ii++) {
        float2 p0 = *(float2*)&acc2[ii][0];
        float2 p1 = *(float2*)&acc2[ii][1];
        float2 p2 = *(float2*)&acc2[ii][2];
        float2 p3 = *(float2*)&acc2[ii][3];
        int m0 = bm + ty * 16 + 2 * ii;
        float4 lo = make_float4(p0.x + bv.x, p1.x + bv.y, p2.x + bv.z, p3.x + bv.w);
        float4 hi = make_float4(p0.y + bv.x, p1.y + bv.y, p2.y + bv.z, p3.y + bv.w);
        *(float4*)(g_up + (size_t)m0 * FIVEH + nbase) = lo;
        *(float4*)(g_up + (size_t)(m0 + 1) * FIVEH + nbase) = hi;
    }
}

// ============================================================================
// Kernel 2: fused URNN core. One block per batch row.
//   FFT/IFFT: Stockham, 5 radix-4 stages + 1 twiddle-free radix-2 stage.
// ============================================================================

__device__ __forceinline__ float2 cmul(float2 a, float2 b) {
    return make_float2(a.x * b.x - a.y * b.y, a.x * b.y + a.y * b.x);
}

// Stockham FFT, N=2048, 256 threads. Radix-4 x5 (m=1,4,16,64,256) then
// radix-2 (m=1024, twiddle = 1). Result lands back in buffer `a`; returned.
// dst[4mj + k + r*m] = (DFT4 of {src[mj+k+q*512]})_r * w^r, w=exp(s*2pi*i*mj/N)
template <int SIGN>
__device__ float2* fft2048(float2* __restrict__ a, float2* __restrict__ b, int tid)
{
    float2* src = a;
    float2* dst = b;
    const float TW = SIGN * 0.0030679615757712823f;   // SIGN * 2*pi / 2048
    int m = 1;

#pragma unroll 1
    for (int st = 0; st < 5; st++) {
#pragma unroll
        for (int q = 0; q < 2; q++) {
            int t = tid + q * 256;               // 0..511
            int k = t & (m - 1);
            float2 c0 = src[t];
            float2 c1 = src[t + 512];
            float2 c2 = src[t + 1024];
            float2 c3 = src[t + 1536];
            float2 s02 = make_float2(c0.x + c2.x, c0.y + c2.y);
            float2 d02 = make_float2(c0.x - c2.x, c0.y - c2.y);
            float2 s13 = make_float2(c1.x + c3.x, c1.y + c3.y);
            float2 d13 = make_float2(c1.x - c3.x, c1.y - c3.y);
            // SIGN*i * d13
            float2 jd13 = (SIGN < 0) ? make_float2(d13.y, -d13.x)
                                     : make_float2(-d13.y, d13.x);
            float2 y0 = make_float2(s02.x + s13.x, s02.y + s13.y);
            float2 y2 = make_float2(s02.x - s13.x, s02.y - s13.y);
            float2 y1 = make_float2(d02.x + jd13.x, d02.y + jd13.y);
            float2 y3 = make_float2(d02.x - jd13.x, d02.y - jd13.y);

            float ang = (float)(t - k) * TW;     // SIGN*2pi*m*j/N
            float sw, cw;
            __sincosf(ang, &sw, &cw);
            float2 w1 = make_float2(cw, sw);
            float2 w2 = make_float2(cw * cw - sw * sw, 2.0f * cw * sw);
            float2 w3 = cmul(w2, w1);

            int d0 = (t << 2) - 3 * k;           // 4*m*j + k
            dst[d0]         = y0;
            dst[d0 + m]     = cmul(y1, w1);
            dst[d0 + 2 * m] = cmul(y2, w2);
            dst[d0 + 3 * m] = cmul(y3, w3);
        }
        __syncthreads();
        float2* tmp = src; src = dst; dst = tmp;
        m <<= 2;
    }

    // final radix-2, m=1024: k=t, j=0 -> twiddle = 1
#pragma unroll
    for (int q = 0; q < 4; q++) {
        int t = tid + q * 256;                   // 0..1023
        float2 c0 = src[t];
        float2 c1 = src[t + 1024];
        dst[t]        = make_float2(c0.x + c1.x, c0.y + c1.y);
        dst[t + 1024] = make_float2(c0.x - c1.x, c0.y - c1.y);
    }
    __syncthreads();
    return dst;
}

__device__ __forceinline__ float2 block_reduce_c2(float2 v, float2* red)
{
#pragma unroll
    for (int off = 16; off > 0; off >>= 1) {
        v.x += __shfl_xor_sync(0xFFFFFFFFu, v.x, off);
        v.y += __shfl_xor_sync(0xFFFFFFFFu, v.y, off);
    }
    __syncthreads();
    int lane = threadIdx.x & 31;
    int w = threadIdx.x >> 5;
    if (lane == 0) red[w] = v;
    __syncthreads();
    float2 sum = make_float2(0.f, 0.f);
#pragma unroll
    for (int i = 0; i < 8; i++) { sum.x += red[i].x; sum.y += red[i].y; }
    return sum;
}

__global__ __launch_bounds__(256) void fused_kernel(
    const float* __restrict__ hxr,
    const float* __restrict__ hxi,
    const int*   __restrict__ perm,
    const float* __restrict__ beta,
    float*       __restrict__ out,
    long long hxLim,
    long long outCap)
{
    __shared__ float2 bufA[HIDDEN];
    __shared__ float2 bufB[HIDDEN];
    __shared__ float2 red[8];

    const int b = blockIdx.x;
    const int tid = threadIdx.x;
    const float* uprow = g_up + (size_t)b * FIVEH;
    const size_t rowoff = (size_t)b * HIDDEN;
    const long long hxLast = hxLim - 1;

    // ---- load: bufA[i] = d1[i] * hx[i] ----
#pragma unroll
    for (int q = 0; q < 8; q++) {
        int i = tid + q * 256;
        float sp, cp;
        __sincosf(uprow[i], &sp, &cp);                 // d1 = (cp, sp)
        long long hidx = ll_min2((long long)(rowoff + i), hxLast);
        float xr = hxr[hidx];
        float xi = hxi[hidx];
        bufA[i] = make_float2(cp * xr - sp * xi, cp * xi + sp * xr);
    }
    __syncthreads();

    // ---- forward FFT ----
    float2* h = fft2048<-1>(bufA, bufB, tid);

    // ---- householder with r1 (plane 3) ----
    float2 rc[8];
    float2 acc = make_float2(0.f, 0.f);
#pragma unroll
    for (int q = 0; q < 8; q++) {
        int i = tid + q * 256;
        float sp, cp;
        __sincosf(uprow[3 * HIDDEN + i], &sp, &cp);
        rc[q] = make_float2(cp, sp);
        float2 hv = h[i];
        acc.x += cp * hv.x + sp * hv.y;
        acc.y += cp * hv.y - sp * hv.x;
    }
    float2 proj = block_reduce_c2(acc, red);
#pragma unroll
    for (int q = 0; q < 8; q++) {
        int i = tid + q * 256;
        float2 rp = cmul(rc[q], proj);
        float2 hv = h[i];
        h[i] = make_float2(hv.x - 2.f * rp.x, hv.y - 2.f * rp.y);
    }
    __syncthreads();

    // ---- gather permutation + d2 (plane 1) ----
    float2* g = (h == bufA) ? bufB : bufA;
#pragma unroll
    for (int q = 0; q < 8; q++) {
        int i = tid + q * 256;
        float sp, cp;
        __sincosf(uprow[HIDDEN + i], &sp, &cp);        // d2
        float2 hv = h[perm[i] & (HIDDEN - 1)];
        g[i] = make_float2(cp * hv.x - sp * hv.y, cp * hv.y + sp * hv.x);
    }
    __syncthreads();

    // ---- inverse FFT (unnormalized; 1/N folded in later) ----
    float2* h2 = fft2048<1>(g, h, tid);

    // ---- householder with r2 (plane 4) ----
    acc = make_float2(0.f, 0.f);
#pragma unroll
    for (int q = 0; q < 8; q++) {
        int i = tid + q * 256;
        float sp, cp;
        __sincosf(uprow[4 * HIDDEN + i], &sp, &cp);
        rc[q] = make_float2(cp, sp);
        float2 hv = h2[i];
        acc.x += cp * hv.x + sp * hv.y;
        acc.y += cp * hv.y - sp * hv.x;
    }
    float2 proj2 = block_reduce_c2(acc, red);

    const float inv = 1.0f / (float)HIDDEN;
#pragma unroll
    for (int q = 0; q < 8; q++) {
        int i = tid + q * 256;
        float2 rp = cmul(rc[q], proj2);
        float2 hv = h2[i];
        float2 v = make_float2(hv.x - 2.f * rp.x, hv.y - 2.f * rp.y);
        // d3 (plane 2) * v * (1/N)
        float sp, cp;
        __sincosf(uprow[2 * HIDDEN + i], &sp, &cp);
        float2 w = make_float2((cp * v.x - sp * v.y) * inv,
                               (cp * v.y + sp * v.x) * inv);
        // ModReLU
        float mag = sqrtf(w.x * w.x + w.y * w.y);
        float nm = fmaxf(mag + beta[i], 0.0f);
        float2 o;
        if (mag > 0.0f) {
            float sc = nm / mag;
            o = make_float2(w.x * sc, w.y * sc);
        } else {
            o = make_float2(nm, 0.0f);
        }

        // ---- output: adaptive layout based on buffer capacity ----
        long long fidx = (long long)(rowoff + i);
        if (outCap >= 2LL * BATCH * HIDDEN) {
            *(float2*)(out + 2 * fidx) = o;     // full complex view
        } else if (fidx < outCap) {
            out[fidx] = o.x;                    // real part (astype f32)
        }
    }
}

// Diagnostic fallback: zero out_size floats (guarded).
__global__ void zero_out_kernel(float* out, long long n)
{
    long long i = (long long)blockIdx.x * blockDim.x + threadIdx.x;
    if (i < n) out[i] = 0.0f;
}

// ============================================================================
// Host: bind inputs BY SIZE (element or byte counts); alphabetical fallback.
// ============================================================================
static inline bool sz_match(long long s, long long elems) {
    return s == elems || s == elems * 4;
}

extern "C" void kernel_launch(void* const* d_in, const int* in_sizes, int n_in,
                              void* d_out, int out_size)
{
    const float* input = nullptr;
    const float* W     = nullptr;
    const float* bias  = nullptr;
    const float* beta  = nullptr;
    const int*   perm  = nullptr;
    const float* hx_first = nullptr;
    const float* hx_second = nullptr;

    long long aLim = (long long)BATCH * INPUT_D;
    long long wLim = (long long)FIVEH * INPUT_D;
    long long bLim = FIVEH;
    long long hxLim = (long long)BATCH * HIDDEN;

    int idx_input = -1, idx_hx_first = -1;

    for (int i = 0; i < n_in; i++) {
        long long s = (long long)in_sizes[i];
        if (sz_match(s, (long long)BATCH * INPUT_D)) {          // 262144
            input = (const float*)d_in[i]; idx_input = i;
        } else if (sz_match(s, (long long)FIVEH * INPUT_D)) {   // 1310720
            W = (const float*)d_in[i];
        } else if (sz_match(s, (long long)FIVEH)) {             // 10240
            bias = (const float*)d_in[i];
        } else if (sz_match(s, (long long)BATCH * HIDDEN)) {    // 4194304
            if (!hx_first) { hx_first = (const float*)d_in[i]; idx_hx_first = i; }
            else           { hx_second = (const float*)d_in[i]; }
        } else if (sz_match(s, (long long)HIDDEN)) {            // 2048
            if (!beta) beta = (const float*)d_in[i];
            else       perm = (const int*)d_in[i];
        }
    }

    const float* hxr = nullptr;
    const float* hxi = nullptr;
    if (hx_first && hx_second) {
        if (idx_input >= 0 && idx_input < idx_hx_first) {
            hxr = hx_first;  hxi = hx_second;   // declared dict order
        } else {
            hxi = hx_first;  hxr = hx_second;   // alphabetical order
        }
    }

    bool ok = input && W && bias && beta && perm && hxr && hxi;

    if (!ok && n_in == 7) {
        // Fallback: alphabetical key order.
        W     = (const float*)d_in[0];
        bias  = (const float*)d_in[1];
        beta  = (const float*)d_in[2];
        hxi   = (const float*)d_in[3];
        hxr   = (const float*)d_in[4];
        input = (const float*)d_in[5];
        perm  = (const int*)d_in[6];
        aLim  = (long long)in_sizes[5] < aLim  ? (long long)in_sizes[5] : aLim;
        wLim  = (long long)in_sizes[0] < wLim  ? (long long)in_sizes[0] : wLim;
        bLim  = (long long)in_sizes[1] < bLim  ? (long long)in_sizes[1] : bLim;
        long long h3 = (long long)in_sizes[3], h4 = (long long)in_sizes[4];
        long long hmin = h3 < h4 ? h3 : h4;
        hxLim = hmin < hxLim ? hmin : hxLim;
        ok = true;
    }

    long long outCap = (long long)out_size;

    if (!ok) {
        long long n = outCap;
        if (n > 0)
            zero_out_kernel<<<(unsigned)((n + 255) / 256), 256>>>((float*)d_out, n);
        return;
    }

    dim3 g1(FIVEH / BN, BATCH / BM);   // (80, 16)
    gemm_kernel<<<g1, 256>>>(input, W, bias, aLim, wLim, bLim);

    fused_kernel<<<BATCH, 256>>>(hxr, hxi, perm, beta, (float*)d_out,
                                 hxLim, outCap);
}

// round 15
// speedup vs baseline: 1.3131x; 1.1219x over previous
#include <cuda_runtime.h>
#include <cuda_bf16.h>
#include <math.h>

#define HIDDEN 2048
#define INPUT_D 128
#define BATCH 2048
#define FIVEH (5 * HIDDEN)

// Scratch for up = input @ W^T + b  (2048 x 10240 f32 = 84MB)
__device__ __align__(16) float g_up[(size_t)BATCH * FIVEH];

__device__ __forceinline__ long long ll_min2(long long a, long long b) {
    return a < b ? a : b;
}

// ============================================================================
// Kernel 1: GEMM via tensor cores (mma.sync m16n8k16 bf16, 3-term split)
//   C[m,n] = sum_k A[m,k]*W[n,k] + bias[n]
//   A (2048,128), W (10240,128) row-major; K=128 fits 4 k-tiles of 32.
//   Split: a = ah + al (bf16 each); C ~= Ah*Wh + Ah*Wl + Al*Wh.
// ============================================================================
#define BM 128
#define BN 128
#define KT 32              // k-tile
#define SROW 40            // smem row stride in bf16 elems (80B, conflict-free)

__device__ __forceinline__ void mma16816(
    float& c0, float& c1, float& c2, float& c3,
    unsigned a0, unsigned a1, unsigned a2, unsigned a3,
    unsigned b0, unsigned b1)
{
    asm volatile(
        "mma.sync.aligned.m16n8k16.row.col.f32.bf16.bf16.f32 "
        "{%0,%1,%2,%3}, {%4,%5,%6,%7}, {%8,%9}, {%0,%1,%2,%3};"
        : "+f"(c0), "+f"(c1), "+f"(c2), "+f"(c3)
        : "r"(a0), "r"(a1), "r"(a2), "r"(a3), "r"(b0), "r"(b1));
}

__global__ __launch_bounds__(256) void gemm_kernel(
    const float* __restrict__ A,
    const float* __restrict__ W,
    const float* __restrict__ bias,
    long long aLim, long long wLim, long long bLim)
{
    __shared__ __nv_bfloat16 As_hi[BM][SROW];
    __shared__ __nv_bfloat16 As_lo[BM][SROW];
    __shared__ __nv_bfloat16 Ws_hi[BN][SROW];
    __shared__ __nv_bfloat16 Ws_lo[BN][SROW];

    const int tid = threadIdx.x;
    const int bn = blockIdx.x * BN;
    const int bm = blockIdx.y * BM;

    const int wid = tid >> 5;
    const int lane = tid & 31;
    const int g = lane >> 2;        // group id (0..7)
    const int t = lane & 3;         // thread-in-group (0..3)
    const int warp_m = wid >> 1;    // 0..3 -> 32 rows each
    const int warp_n = wid & 1;     // 0..1 -> 64 cols each
    const int Rm = warp_m * 32;
    const int Cn = warp_n * 64;

    const long long aLast = (aLim & ~3LL) - 4;
    const long long wLast = (wLim & ~3LL) - 4;
    const long long bLast = bLim - 1;

    // acc[mt][nt][4]: mt in 0..1 (16 rows), nt in 0..7 (8 cols)
    float acc[2][8][4];
#pragma unroll
    for (int i = 0; i < 2; i++)
#pragma unroll
        for (int j = 0; j < 8; j++)
#pragma unroll
            for (int r = 0; r < 4; r++) acc[i][j][r] = 0.0f;

    const int lrow = tid >> 1;            // 0..127 (smem row this thread fills)
    const int lcb  = (tid & 1) * 16;      // k col base (0 or 16)

    for (int kt = 0; kt < INPUT_D; kt += KT) {
        // ---- load + split A and W tiles into bf16 hi/lo smem ----
#pragma unroll
        for (int f = 0; f < 4; f++) {
            int kc = lcb + f * 4;
            long long aoff = ll_min2((long long)(bm + lrow) * INPUT_D + kt + kc, aLast);
            float4 va = *(const float4*)(A + aoff);
            float av[4] = {va.x, va.y, va.z, va.w};
#pragma unroll
            for (int e = 0; e < 4; e += 2) {
                __nv_bfloat16 h0 = __float2bfloat16(av[e]);
                __nv_bfloat16 h1 = __float2bfloat16(av[e + 1]);
                __nv_bfloat16 l0 = __float2bfloat16(av[e] - __bfloat162float(h0));
                __nv_bfloat16 l1 = __float2bfloat16(av[e + 1] - __bfloat162float(h1));
                *(__nv_bfloat162*)&As_hi[lrow][kc + e] = make_bfloat162(h0, h1);
                *(__nv_bfloat162*)&As_lo[lrow][kc + e] = make_bfloat162(l0, l1);
            }
            long long woff = ll_min2((long long)(bn + lrow) * INPUT_D + kt + kc, wLast);
            float4 vw = *(const float4*)(W + woff);
            float wv[4] = {vw.x, vw.y, vw.z, vw.w};
#pragma unroll
            for (int e = 0; e < 4; e += 2) {
                __nv_bfloat16 h0 = __float2bfloat16(wv[e]);
                __nv_bfloat16 h1 = __float2bfloat16(wv[e + 1]);
                __nv_bfloat16 l0 = __float2bfloat16(wv[e] - __bfloat162float(h0));
                __nv_bfloat16 l1 = __float2bfloat16(wv[e + 1] - __bfloat162float(h1));
                *(__nv_bfloat162*)&Ws_hi[lrow][kc + e] = make_bfloat162(h0, h1);
                *(__nv_bfloat162*)&Ws_lo[lrow][kc + e] = make_bfloat162(l0, l1);
            }
        }
        __syncthreads();

        // ---- 2 k16 steps per tile ----
#pragma unroll
        for (int s = 0; s < 2; s++) {
            int ks = s * 16 + 2 * t;          // fragment k base for this lane

            unsigned ah[2][4], al[2][4];
#pragma unroll
            for (int mt = 0; mt < 2; mt++) {
                int r = Rm + mt * 16 + g;
                ah[mt][0] = *(unsigned*)&As_hi[r][ks];
                ah[mt][1] = *(unsigned*)&As_hi[r + 8][ks];
                ah[mt][2] = *(unsigned*)&As_hi[r][ks + 8];
                ah[mt][3] = *(unsigned*)&As_hi[r + 8][ks + 8];
                al[mt][0] = *(unsigned*)&As_lo[r][ks];
                al[mt][1] = *(unsigned*)&As_lo[r + 8][ks];
                al[mt][2] = *(unsigned*)&As_lo[r][ks + 8];
                al[mt][3] = *(unsigned*)&As_lo[r + 8][ks + 8];
            }
            unsigned bh[8][2], bl[8][2];
#pragma unroll
            for (int nt = 0; nt < 8; nt++) {
                int c = Cn + nt * 8 + g;
                bh[nt][0] = *(unsigned*)&Ws_hi[c][ks];
                bh[nt][1] = *(unsigned*)&Ws_hi[c][ks + 8];
                bl[nt][0] = *(unsigned*)&Ws_lo[c][ks];
                bl[nt][1] = *(unsigned*)&Ws_lo[c][ks + 8];
            }
#pragma unroll
            for (int mt = 0; mt < 2; mt++)
#pragma unroll
                for (int nt = 0; nt < 8; nt++) {
                    float* cc = acc[mt][nt];
                    mma16816(cc[0], cc[1], cc[2], cc[3],
                             ah[mt][0], ah[mt][1], ah[mt][2], ah[mt][3],
                             bh[nt][0], bh[nt][1]);
                    mma16816(cc[0], cc[1], cc[2], cc[3],
                             ah[mt][0], ah[mt][1], ah[mt][2], ah[mt][3],
                             bl[nt][0], bl[nt][1]);
                    mma16816(cc[0], cc[1], cc[2], cc[3],
                             al[mt][0], al[mt][1], al[mt][2], al[mt][3],
                             bh[nt][0], bh[nt][1]);
                }
        }
        __syncthreads();
    }

    // ---- epilogue: add bias, write f32 ----
#pragma unroll
    for (int nt = 0; nt < 8; nt++) {
        long long col = bn + Cn + nt * 8 + 2 * t;
        float b0 = bias[ll_min2(col, bLast)];
        float b1 = bias[ll_min2(col + 1, bLast)];
#pragma unroll
        for (int mt = 0; mt < 2; mt++) {
            int row = bm + Rm + mt * 16 + g;
            float* cc = acc[mt][nt];
            *(float2*)(g_up + (size_t)row * FIVEH + col) =
                make_float2(cc[0] + b0, cc[1] + b1);
            *(float2*)(g_up + (size_t)(row + 8) * FIVEH + col) =
                make_float2(cc[2] + b0, cc[3] + b1);
        }
    }
}

// ============================================================================
// Kernel 2: fused URNN core. One block per batch row.
//   FFT/IFFT: Stockham, 5 radix-4 stages + 1 twiddle-free radix-2 stage.
// ============================================================================

__device__ __forceinline__ float2 cmul(float2 a, float2 b) {
    return make_float2(a.x * b.x - a.y * b.y, a.x * b.y + a.y * b.x);
}

template <int SIGN>
__device__ float2* fft2048(float2* __restrict__ a, float2* __restrict__ b, int tid)
{
    float2* src = a;
    float2* dst = b;
    const float TW = SIGN * 0.0030679615757712823f;   // SIGN * 2*pi / 2048
    int m = 1;

#pragma unroll 1
    for (int st = 0; st < 5; st++) {
#pragma unroll
        for (int q = 0; q < 2; q++) {
            int t = tid + q * 256;               // 0..511
            int k = t & (m - 1);
            float2 c0 = src[t];
            float2 c1 = src[t + 512];
            float2 c2 = src[t + 1024];
            float2 c3 = src[t + 1536];
            float2 s02 = make_float2(c0.x + c2.x, c0.y + c2.y);
            float2 d02 = make_float2(c0.x - c2.x, c0.y - c2.y);
            float2 s13 = make_float2(c1.x + c3.x, c1.y + c3.y);
            float2 d13 = make_float2(c1.x - c3.x, c1.y - c3.y);
            float2 jd13 = (SIGN < 0) ? make_float2(d13.y, -d13.x)
                                     : make_float2(-d13.y, d13.x);
            float2 y0 = make_float2(s02.x + s13.x, s02.y + s13.y);
            float2 y2 = make_float2(s02.x - s13.x, s02.y - s13.y);
            float2 y1 = make_float2(d02.x + jd13.x, d02.y + jd13.y);
            float2 y3 = make_float2(d02.x - jd13.x, d02.y - jd13.y);

            float ang = (float)(t - k) * TW;
            float sw, cw;
            __sincosf(ang, &sw, &cw);
            float2 w1 = make_float2(cw, sw);
            float2 w2 = make_float2(cw * cw - sw * sw, 2.0f * cw * sw);
            float2 w3 = cmul(w2, w1);

            int d0 = (t << 2) - 3 * k;
            dst[d0]         = y0;
            dst[d0 + m]     = cmul(y1, w1);
            dst[d0 + 2 * m] = cmul(y2, w2);
            dst[d0 + 3 * m] = cmul(y3, w3);
        }
        __syncthreads();
        float2* tmp = src; src = dst; dst = tmp;
        m <<= 2;
    }

    // final radix-2, m=1024: twiddle = 1
#pragma unroll
    for (int q = 0; q < 4; q++) {
        int t = tid + q * 256;
        float2 c0 = src[t];
        float2 c1 = src[t + 1024];
        dst[t]        = make_float2(c0.x + c1.x, c0.y + c1.y);
        dst[t + 1024] = make_float2(c0.x - c1.x, c0.y - c1.y);
    }
    __syncthreads();
    return dst;
}

__device__ __forceinline__ float2 block_reduce_c2(float2 v, float2* red)
{
#pragma unroll
    for (int off = 16; off > 0; off >>= 1) {
        v.x += __shfl_xor_sync(0xFFFFFFFFu, v.x, off);
        v.y += __shfl_xor_sync(0xFFFFFFFFu, v.y, off);
    }
    __syncthreads();
    int lane = threadIdx.x & 31;
    int w = threadIdx.x >> 5;
    if (lane == 0) red[w] = v;
    __syncthreads();
    float2 sum = make_float2(0.f, 0.f);
#pragma unroll
    for (int i = 0; i < 8; i++) { sum.x += red[i].x; sum.y += red[i].y; }
    return sum;
}

__global__ __launch_bounds__(256) void fused_kernel(
    const float* __restrict__ hxr,
    const float* __restrict__ hxi,
    const int*   __restrict__ perm,
    const float* __restrict__ beta,
    float*       __restrict__ out,
    long long hxLim,
    long long outCap)
{
    __shared__ float2 bufA[HIDDEN];
    __shared__ float2 bufB[HIDDEN];
    __shared__ float2 red[8];

    const int b = blockIdx.x;
    const int tid = threadIdx.x;
    const float* uprow = g_up + (size_t)b * FIVEH;
    const size_t rowoff = (size_t)b * HIDDEN;
    const long long hxLast = hxLim - 1;

#pragma unroll
    for (int q = 0; q < 8; q++) {
        int i = tid + q * 256;
        float sp, cp;
        __sincosf(uprow[i], &sp, &cp);                 // d1 = (cp, sp)
        long long hidx = ll_min2((long long)(rowoff + i), hxLast);
        float xr = hxr[hidx];
        float xi = hxi[hidx];
        bufA[i] = make_float2(cp * xr - sp * xi, cp * xi + sp * xr);
    }
    __syncthreads();

    float2* h = fft2048<-1>(bufA, bufB, tid);

    float2 rc[8];
    float2 acc = make_float2(0.f, 0.f);
#pragma unroll
    for (int q = 0; q < 8; q++) {
        int i = tid + q * 256;
        float sp, cp;
        __sincosf(uprow[3 * HIDDEN + i], &sp, &cp);
        rc[q] = make_float2(cp, sp);
        float2 hv = h[i];
        acc.x += cp * hv.x + sp * hv.y;
        acc.y += cp * hv.y - sp * hv.x;
    }
    float2 proj = block_reduce_c2(acc, red);
#pragma unroll
    for (int q = 0; q < 8; q++) {
        int i = tid + q * 256;
        float2 rp = cmul(rc[q], proj);
        float2 hv = h[i];
        h[i] = make_float2(hv.x - 2.f * rp.x, hv.y - 2.f * rp.y);
    }
    __syncthreads();

    float2* g = (h == bufA) ? bufB : bufA;
#pragma unroll
    for (int q = 0; q < 8; q++) {
        int i = tid + q * 256;
        float sp, cp;
        __sincosf(uprow[HIDDEN + i], &sp, &cp);        // d2
        float2 hv = h[perm[i] & (HIDDEN - 1)];
        g[i] = make_float2(cp * hv.x - sp * hv.y, cp * hv.y + sp * hv.x);
    }
    __syncthreads();

    float2* h2 = fft2048<1>(g, h, tid);

    acc = make_float2(0.f, 0.f);
#pragma unroll
    for (int q = 0; q < 8; q++) {
        int i = tid + q * 256;
        float sp, cp;
        __sincosf(uprow[4 * HIDDEN + i], &sp, &cp);
        rc[q] = make_float2(cp, sp);
        float2 hv = h2[i];
        acc.x += cp * hv.x + sp * hv.y;
        acc.y += cp * hv.y - sp * hv.x;
    }
    float2 proj2 = block_reduce_c2(acc, red);

    const float inv = 1.0f / (float)HIDDEN;
#pragma unroll
    for (int q = 0; q < 8; q++) {
        int i = tid + q * 256;
        float2 rp = cmul(rc[q], proj2);
        float2 hv = h2[i];
        float2 v = make_float2(hv.x - 2.f * rp.x, hv.y - 2.f * rp.y);
        float sp, cp;
        __sincosf(uprow[2 * HIDDEN + i], &sp, &cp);
        float2 w = make_float2((cp * v.x - sp * v.y) * inv,
                               (cp * v.y + sp * v.x) * inv);
        float mag = sqrtf(w.x * w.x + w.y * w.y);
        float nm = fmaxf(mag + beta[i], 0.0f);
        float2 o;
        if (mag > 0.0f) {
            float sc = nm / mag;
            o = make_float2(w.x * sc, w.y * sc);
        } else {
            o = make_float2(nm, 0.0f);
        }

        long long fidx = (long long)(rowoff + i);
        if (outCap >= 2LL * BATCH * HIDDEN) {
            *(float2*)(out + 2 * fidx) = o;     // full complex view
        } else if (fidx < outCap) {
            out[fidx] = o.x;                    // real part (astype f32)
        }
    }
}

__global__ void zero_out_kernel(float* out, long long n)
{
    long long i = (long long)blockIdx.x * blockDim.x + threadIdx.x;
    if (i < n) out[i] = 0.0f;
}

// ============================================================================
// Host: bind inputs BY SIZE (element or byte counts); alphabetical fallback.
// ============================================================================
static inline bool sz_match(long long s, long long elems) {
    return s == elems || s == elems * 4;
}

extern "C" void kernel_launch(void* const* d_in, const int* in_sizes, int n_in,
                              void* d_out, int out_size)
{
    const float* input = nullptr;
    const float* W     = nullptr;
    const float* bias  = nullptr;
    const float* beta  = nullptr;
    const int*   perm  = nullptr;
    const float* hx_first = nullptr;
    const float* hx_second = nullptr;

    long long aLim = (long long)BATCH * INPUT_D;
    long long wLim = (long long)FIVEH * INPUT_D;
    long long bLim = FIVEH;
    long long hxLim = (long long)BATCH * HIDDEN;

    int idx_input = -1, idx_hx_first = -1;

    for (int i = 0; i < n_in; i++) {
        long long s = (long long)in_sizes[i];
        if (sz_match(s, (long long)BATCH * INPUT_D)) {
            input = (const float*)d_in[i]; idx_input = i;
        } else if (sz_match(s, (long long)FIVEH * INPUT_D)) {
            W = (const float*)d_in[i];
        } else if (sz_match(s, (long long)FIVEH)) {
            bias = (const float*)d_in[i];
        } else if (sz_match(s, (long long)BATCH * HIDDEN)) {
            if (!hx_first) { hx_first = (const float*)d_in[i]; idx_hx_first = i; }
            else           { hx_second = (const float*)d_in[i]; }
        } else if (sz_match(s, (long long)HIDDEN)) {
            if (!beta) beta = (const float*)d_in[i];
            else       perm = (const int*)d_in[i];
        }
    }

    const float* hxr = nullptr;
    const float* hxi = nullptr;
    if (hx_first && hx_second) {
        if (idx_input >= 0 && idx_input < idx_hx_first) {
            hxr = hx_first;  hxi = hx_second;   // declared dict order
        } else {
            hxi = hx_first;  hxr = hx_second;   // alphabetical order
        }
    }

    bool ok = input && W && bias && beta && perm && hxr && hxi;

    if (!ok && n_in == 7) {
        W     = (const float*)d_in[0];
        bias  = (const float*)d_in[1];
        beta  = (const float*)d_in[2];
        hxi   = (const float*)d_in[3];
        hxr   = (const float*)d_in[4];
        input = (const float*)d_in[5];
        perm  = (const int*)d_in[6];
        aLim  = (long long)in_sizes[5] < aLim  ? (long long)in_sizes[5] : aLim;
        wLim  = (long long)in_sizes[0] < wLim  ? (long long)in_sizes[0] : wLim;
        bLim  = (long long)in_sizes[1] < bLim  ? (long long)in_sizes[1] : bLim;
        long long h3 = (long long)in_sizes[3], h4 = (long long)in_sizes[4];
        long long hmin = h3 < h4 ? h3 : h4;
        hxLim = hmin < hxLim ? hmin : hxLim;
        ok = true;
    }

    long long outCap = (long long)out_size;

    if (!ok) {
        long long n = outCap;
        if (n > 0)
            zero_out_kernel<<<(unsigned)((n + 255) / 256), 256>>>((float*)d_out, n);
        return;
    }

    dim3 g1(FIVEH / BN, BATCH / BM);   // (80, 16)
    gemm_kernel<<<g1, 256>>>(input, W, bias, aLim, wLim, bLim);

    fused_kernel<<<BATCH, 256>>>(hxr, hxi, perm, beta, (float*)d_out,
                                 hxLim, outCap);
}

// round 16
// speedup vs baseline: 1.5915x; 1.2120x over previous
#include <cuda_runtime.h>
#include <cuda_bf16.h>
#include <math.h>

#define HIDDEN 2048
#define INPUT_D 128
#define BATCH 2048
#define FIVEH (5 * HIDDEN)

// Scratch for up = input @ W^T + b  (2048 x 10240 f32 = 84MB)
__device__ __align__(16) float g_up[(size_t)BATCH * FIVEH];

// Pre-split bf16 operands (hi + lo residual)
__device__ __align__(16) __nv_bfloat16 g_Ahi[(size_t)BATCH * INPUT_D];
__device__ __align__(16) __nv_bfloat16 g_Alo[(size_t)BATCH * INPUT_D];
__device__ __align__(16) __nv_bfloat16 g_Whi[(size_t)FIVEH * INPUT_D];
__device__ __align__(16) __nv_bfloat16 g_Wlo[(size_t)FIVEH * INPUT_D];

__device__ __forceinline__ long long ll_min2(long long a, long long b) {
    return a < b ? a : b;
}

// ============================================================================
// Split kernel: f32 -> bf16 hi + bf16 lo (residual), vectorized x4.
// ============================================================================
__global__ void split_kernel(const float* __restrict__ src,
                             __nv_bfloat16* __restrict__ hi,
                             __nv_bfloat16* __restrict__ lo,
                             long long n, long long srcLast4)
{
    long long i = 4LL * ((long long)blockIdx.x * blockDim.x + threadIdx.x);
    if (i >= n) return;
    long long off = ll_min2(i, srcLast4);
    float4 v = *(const float4*)(src + off);
    float a[4] = {v.x, v.y, v.z, v.w};
    __nv_bfloat16 h[4], l[4];
#pragma unroll
    for (int e = 0; e < 4; e++) {
        h[e] = __float2bfloat16(a[e]);
        l[e] = __float2bfloat16(a[e] - __bfloat162float(h[e]));
    }
    *(__nv_bfloat162*)&hi[i]     = make_bfloat162(h[0], h[1]);
    *(__nv_bfloat162*)&hi[i + 2] = make_bfloat162(h[2], h[3]);
    *(__nv_bfloat162*)&lo[i]     = make_bfloat162(l[0], l[1]);
    *(__nv_bfloat162*)&lo[i + 2] = make_bfloat162(l[2], l[3]);
}

// ============================================================================
// Kernel 1: GEMM via tensor cores (mma m16n8k16 bf16, pre-split 3-term)
//   C = Ah*Wh + Ah*Wl + Al*Wh  (+bias). ldmatrix fragment loads.
// ============================================================================
#define BM 128
#define BN 128
#define KT 32
#define SROW 40            // bf16 elems per smem row (80B; LDSM conflict-free)

__device__ __forceinline__ void mma16816(
    float& c0, float& c1, float& c2, float& c3,
    unsigned a0, unsigned a1, unsigned a2, unsigned a3,
    unsigned b0, unsigned b1)
{
    asm volatile(
        "mma.sync.aligned.m16n8k16.row.col.f32.bf16.bf16.f32 "
        "{%0,%1,%2,%3}, {%4,%5,%6,%7}, {%8,%9}, {%0,%1,%2,%3};"
        : "+f"(c0), "+f"(c1), "+f"(c2), "+f"(c3)
        : "r"(a0), "r"(a1), "r"(a2), "r"(a3), "r"(b0), "r"(b1));
}

__device__ __forceinline__ void ldsm_x4(unsigned& r0, unsigned& r1,
                                        unsigned& r2, unsigned& r3,
                                        const void* p)
{
    unsigned addr = (unsigned)__cvta_generic_to_shared(p);
    asm volatile("ldmatrix.sync.aligned.m8n8.x4.shared.b16 {%0,%1,%2,%3}, [%4];"
                 : "=r"(r0), "=r"(r1), "=r"(r2), "=r"(r3) : "r"(addr));
}

__global__ __launch_bounds__(256) void gemm_kernel(
    const __nv_bfloat16* __restrict__ Ahi,
    const __nv_bfloat16* __restrict__ Alo,
    const __nv_bfloat16* __restrict__ Whi,
    const __nv_bfloat16* __restrict__ Wlo,
    const float* __restrict__ bias, long long bLast)
{
    __shared__ __nv_bfloat16 As_hi[BM][SROW];
    __shared__ __nv_bfloat16 As_lo[BM][SROW];
    __shared__ __nv_bfloat16 Ws_hi[BN][SROW];
    __shared__ __nv_bfloat16 Ws_lo[BN][SROW];

    const int tid = threadIdx.x;
    const int bn = blockIdx.x * BN;
    const int bm = blockIdx.y * BM;

    const int wid = tid >> 5;
    const int lane = tid & 31;
    const int g = lane >> 2;
    const int t = lane & 3;
    const int Rm = (wid >> 1) * 32;     // 4 warp-rows of 32
    const int Cn = (wid & 1) * 64;      // 2 warp-cols of 64

    const int quad = lane >> 3;         // ldmatrix addressing
    const int ln = lane & 7;

    float acc[2][8][4];
#pragma unroll
    for (int i = 0; i < 2; i++)
#pragma unroll
        for (int j = 0; j < 8; j++)
#pragma unroll
            for (int r = 0; r < 4; r++) acc[i][j][r] = 0.0f;

    const int lrow = tid >> 1;          // fill: smem row
    const int lkc  = (tid & 1) * 16;    // fill: k col base (0/16)

    for (int kt = 0; kt < INPUT_D; kt += KT) {
        // ---- fill: pure uint4 copies of pre-split bf16 ----
        {
            size_t aoff = (size_t)(bm + lrow) * INPUT_D + kt + lkc;
            *(uint4*)&As_hi[lrow][lkc]     = *(const uint4*)(Ahi + aoff);
            *(uint4*)&As_hi[lrow][lkc + 8] = *(const uint4*)(Ahi + aoff + 8);
            *(uint4*)&As_lo[lrow][lkc]     = *(const uint4*)(Alo + aoff);
            *(uint4*)&As_lo[lrow][lkc + 8] = *(const uint4*)(Alo + aoff + 8);
            size_t woff = (size_t)(bn + lrow) * INPUT_D + kt + lkc;
            *(uint4*)&Ws_hi[lrow][lkc]     = *(const uint4*)(Whi + woff);
            *(uint4*)&Ws_hi[lrow][lkc + 8] = *(const uint4*)(Whi + woff + 8);
            *(uint4*)&Ws_lo[lrow][lkc]     = *(const uint4*)(Wlo + woff);
            *(uint4*)&Ws_lo[lrow][lkc + 8] = *(const uint4*)(Wlo + woff + 8);
        }
        __syncthreads();

#pragma unroll
        for (int s = 0; s < 2; s++) {
            const int ks0 = s * 16;

            // A fragments: rows Rm + mt*16 + {ln, +8}, k = ks0 + {0,8}
            const int arow = ln + (quad & 1) * 8;
            const int akc = ks0 + (quad >> 1) * 8;
            unsigned ah[2][4], al[2][4];
#pragma unroll
            for (int mt = 0; mt < 2; mt++) {
                int r = Rm + mt * 16 + arow;
                ldsm_x4(ah[mt][0], ah[mt][1], ah[mt][2], ah[mt][3],
                        &As_hi[r][akc]);
                ldsm_x4(al[mt][0], al[mt][1], al[mt][2], al[mt][3],
                        &As_lo[r][akc]);
            }

            // B fragments: 16 n-rows per LDSM.x4
            const int brow = ln + (quad >> 1) * 8;
            const int bkc = ks0 + (quad & 1) * 8;
            unsigned bh[8][2], bl[8][2];
#pragma unroll
            for (int ntp = 0; ntp < 4; ntp++) {
                int c = Cn + ntp * 16 + brow;
                ldsm_x4(bh[2 * ntp][0], bh[2 * ntp][1],
                        bh[2 * ntp + 1][0], bh[2 * ntp + 1][1],
                        &Ws_hi[c][bkc]);
                ldsm_x4(bl[2 * ntp][0], bl[2 * ntp][1],
                        bl[2 * ntp + 1][0], bl[2 * ntp + 1][1],
                        &Ws_lo[c][bkc]);
            }

#pragma unroll
            for (int mt = 0; mt < 2; mt++)
#pragma unroll
                for (int nt = 0; nt < 8; nt++) {
                    float* cc = acc[mt][nt];
                    mma16816(cc[0], cc[1], cc[2], cc[3],
                             ah[mt][0], ah[mt][1], ah[mt][2], ah[mt][3],
                             bh[nt][0], bh[nt][1]);
                    mma16816(cc[0], cc[1], cc[2], cc[3],
                             ah[mt][0], ah[mt][1], ah[mt][2], ah[mt][3],
                             bl[nt][0], bl[nt][1]);
                    mma16816(cc[0], cc[1], cc[2], cc[3],
                             al[mt][0], al[mt][1], al[mt][2], al[mt][3],
                             bh[nt][0], bh[nt][1]);
                }
        }
        __syncthreads();
    }

    // ---- epilogue: add bias, write f32 ----
#pragma unroll
    for (int nt = 0; nt < 8; nt++) {
        long long col = bn + Cn + nt * 8 + 2 * t;
        float b0 = bias[ll_min2(col, bLast)];
        float b1 = bias[ll_min2(col + 1, bLast)];
#pragma unroll
        for (int mt = 0; mt < 2; mt++) {
            int row = bm + Rm + mt * 16 + g;
            float* cc = acc[mt][nt];
            *(float2*)(g_up + (size_t)row * FIVEH + col) =
                make_float2(cc[0] + b0, cc[1] + b1);
            *(float2*)(g_up + (size_t)(row + 8) * FIVEH + col) =
                make_float2(cc[2] + b0, cc[3] + b1);
        }
    }
}

// ============================================================================
// Kernel 2: fused URNN core (FROZEN from round 14). One block per batch row.
// ============================================================================

__device__ __forceinline__ float2 cmul(float2 a, float2 b) {
    return make_float2(a.x * b.x - a.y * b.y, a.x * b.y + a.y * b.x);
}

template <int SIGN>
__device__ float2* fft2048(float2* __restrict__ a, float2* __restrict__ b, int tid)
{
    float2* src = a;
    float2* dst = b;
    const float TW = SIGN * 0.0030679615757712823f;   // SIGN * 2*pi / 2048
    int m = 1;

#pragma unroll 1
    for (int st = 0; st < 5; st++) {
#pragma unroll
        for (int q = 0; q < 2; q++) {
            int t = tid + q * 256;
            int k = t & (m - 1);
            float2 c0 = src[t];
            float2 c1 = src[t + 512];
            float2 c2 = src[t + 1024];
            float2 c3 = src[t + 1536];
            float2 s02 = make_float2(c0.x + c2.x, c0.y + c2.y);
            float2 d02 = make_float2(c0.x - c2.x, c0.y - c2.y);
            float2 s13 = make_float2(c1.x + c3.x, c1.y + c3.y);
            float2 d13 = make_float2(c1.x - c3.x, c1.y - c3.y);
            float2 jd13 = (SIGN < 0) ? make_float2(d13.y, -d13.x)
                                     : make_float2(-d13.y, d13.x);
            float2 y0 = make_float2(s02.x + s13.x, s02.y + s13.y);
            float2 y2 = make_float2(s02.x - s13.x, s02.y - s13.y);
            float2 y1 = make_float2(d02.x + jd13.x, d02.y + jd13.y);
            float2 y3 = make_float2(d02.x - jd13.x, d02.y - jd13.y);

            float ang = (float)(t - k) * TW;
            float sw, cw;
            __sincosf(ang, &sw, &cw);
            float2 w1 = make_float2(cw, sw);
            float2 w2 = make_float2(cw * cw - sw * sw, 2.0f * cw * sw);
            float2 w3 = cmul(w2, w1);

            int d0 = (t << 2) - 3 * k;
            dst[d0]         = y0;
            dst[d0 + m]     = cmul(y1, w1);
            dst[d0 + 2 * m] = cmul(y2, w2);
            dst[d0 + 3 * m] = cmul(y3, w3);
        }
        __syncthreads();
        float2* tmp = src; src = dst; dst = tmp;
        m <<= 2;
    }

#pragma unroll
    for (int q = 0; q < 4; q++) {
        int t = tid + q * 256;
        float2 c0 = src[t];
        float2 c1 = src[t + 1024];
        dst[t]        = make_float2(c0.x + c1.x, c0.y + c1.y);
        dst[t + 1024] = make_float2(c0.x - c1.x, c0.y - c1.y);
    }
    __syncthreads();
    return dst;
}

__device__ __forceinline__ float2 block_reduce_c2(float2 v, float2* red)
{
#pragma unroll
    for (int off = 16; off > 0; off >>= 1) {
        v.x += __shfl_xor_sync(0xFFFFFFFFu, v.x, off);
        v.y += __shfl_xor_sync(0xFFFFFFFFu, v.y, off);
    }
    __syncthreads();
    int lane = threadIdx.x & 31;
    int w = threadIdx.x >> 5;
    if (lane == 0) red[w] = v;
    __syncthreads();
    float2 sum = make_float2(0.f, 0.f);
#pragma unroll
    for (int i = 0; i < 8; i++) { sum.x += red[i].x; sum.y += red[i].y; }
    return sum;
}

__global__ __launch_bounds__(256) void fused_kernel(
    const float* __restrict__ hxr,
    const float* __restrict__ hxi,
    const int*   __restrict__ perm,
    const float* __restrict__ beta,
    float*       __restrict__ out,
    long long hxLim,
    long long outCap)
{
    __shared__ float2 bufA[HIDDEN];
    __shared__ float2 bufB[HIDDEN];
    __shared__ float2 red[8];

    const int b = blockIdx.x;
    const int tid = threadIdx.x;
    const float* uprow = g_up + (size_t)b * FIVEH;
    const size_t rowoff = (size_t)b * HIDDEN;
    const long long hxLast = hxLim - 1;

#pragma unroll
    for (int q = 0; q < 8; q++) {
        int i = tid + q * 256;
        float sp, cp;
        __sincosf(uprow[i], &sp, &cp);                 // d1 = (cp, sp)
        long long hidx = ll_min2((long long)(rowoff + i), hxLast);
        float xr = hxr[hidx];
        float xi = hxi[hidx];
        bufA[i] = make_float2(cp * xr - sp * xi, cp * xi + sp * xr);
    }
    __syncthreads();

    float2* h = fft2048<-1>(bufA, bufB, tid);

    float2 rc[8];
    float2 acc = make_float2(0.f, 0.f);
#pragma unroll
    for (int q = 0; q < 8; q++) {
        int i = tid + q * 256;
        float sp, cp;
        __sincosf(uprow[3 * HIDDEN + i], &sp, &cp);
        rc[q] = make_float2(cp, sp);
        float2 hv = h[i];
        acc.x += cp * hv.x + sp * hv.y;
        acc.y += cp * hv.y - sp * hv.x;
    }
    float2 proj = block_reduce_c2(acc, red);
#pragma unroll
    for (int q = 0; q < 8; q++) {
        int i = tid + q * 256;
        float2 rp = cmul(rc[q], proj);
        float2 hv = h[i];
        h[i] = make_float2(hv.x - 2.f * rp.x, hv.y - 2.f * rp.y);
    }
    __syncthreads();

    float2* g = (h == bufA) ? bufB : bufA;
#pragma unroll
    for (int q = 0; q < 8; q++) {
        int i = tid + q * 256;
        float sp, cp;
        __sincosf(uprow[HIDDEN + i], &sp, &cp);        // d2
        float2 hv = h[perm[i] & (HIDDEN - 1)];
        g[i] = make_float2(cp * hv.x - sp * hv.y, cp * hv.y + sp * hv.x);
    }
    __syncthreads();

    float2* h2 = fft2048<1>(g, h, tid);

    acc = make_float2(0.f, 0.f);
#pragma unroll
    for (int q = 0; q < 8; q++) {
        int i = tid + q * 256;
        float sp, cp;
        __sincosf(uprow[4 * HIDDEN + i], &sp, &cp);
        rc[q] = make_float2(cp, sp);
        float2 hv = h2[i];
        acc.x += cp * hv.x + sp * hv.y;
        acc.y += cp * hv.y - sp * hv.x;
    }
    float2 proj2 = block_reduce_c2(acc, red);

    const float inv = 1.0f / (float)HIDDEN;
#pragma unroll
    for (int q = 0; q < 8; q++) {
        int i = tid + q * 256;
        float2 rp = cmul(rc[q], proj2);
        float2 hv = h2[i];
        float2 v = make_float2(hv.x - 2.f * rp.x, hv.y - 2.f * rp.y);
        float sp, cp;
        __sincosf(uprow[2 * HIDDEN + i], &sp, &cp);
        float2 w = make_float2((cp * v.x - sp * v.y) * inv,
                               (cp * v.y + sp * v.x) * inv);
        float mag = sqrtf(w.x * w.x + w.y * w.y);
        float nm = fmaxf(mag + beta[i], 0.0f);
        float2 o;
        if (mag > 0.0f) {
            float sc = nm / mag;
            o = make_float2(w.x * sc, w.y * sc);
        } else {
            o = make_float2(nm, 0.0f);
        }

        long long fidx = (long long)(rowoff + i);
        if (outCap >= 2LL * BATCH * HIDDEN) {
            *(float2*)(out + 2 * fidx) = o;     // full complex view
        } else if (fidx < outCap) {
            out[fidx] = o.x;                    // real part (astype f32)
        }
    }
}

__global__ void zero_out_kernel(float* out, long long n)
{
    long long i = (long long)blockIdx.x * blockDim.x + threadIdx.x;
    if (i < n) out[i] = 0.0f;
}

// ============================================================================
// Host: bind inputs BY SIZE (element or byte counts); alphabetical fallback.
// ============================================================================
static inline bool sz_match(long long s, long long elems) {
    return s == elems || s == elems * 4;
}

extern "C" void kernel_launch(void* const* d_in, const int* in_sizes, int n_in,
                              void* d_out, int out_size)
{
    const float* input = nullptr;
    const float* W     = nullptr;
    const float* bias  = nullptr;
    const float* beta  = nullptr;
    const int*   perm  = nullptr;
    const float* hx_first = nullptr;
    const float* hx_second = nullptr;

    long long aLim = (long long)BATCH * INPUT_D;
    long long wLim = (long long)FIVEH * INPUT_D;
    long long bLim = FIVEH;
    long long hxLim = (long long)BATCH * HIDDEN;

    int idx_input = -1, idx_hx_first = -1;

    for (int i = 0; i < n_in; i++) {
        long long s = (long long)in_sizes[i];
        if (sz_match(s, (long long)BATCH * INPUT_D)) {
            input = (const float*)d_in[i]; idx_input = i;
        } else if (sz_match(s, (long long)FIVEH * INPUT_D)) {
            W = (const float*)d_in[i];
        } else if (sz_match(s, (long long)FIVEH)) {
            bias = (const float*)d_in[i];
        } else if (sz_match(s, (long long)BATCH * HIDDEN)) {
            if (!hx_first) { hx_first = (const float*)d_in[i]; idx_hx_first = i; }
            else           { hx_second = (const float*)d_in[i]; }
        } else if (sz_match(s, (long long)HIDDEN)) {
            if (!beta) beta = (const float*)d_in[i];
            else       perm = (const int*)d_in[i];
        }
    }

    const float* hxr = nullptr;
    const float* hxi = nullptr;
    if (hx_first && hx_second) {
        if (idx_input >= 0 && idx_input < idx_hx_first) {
            hxr = hx_first;  hxi = hx_second;   // declared dict order
        } else {
            hxi = hx_first;  hxr = hx_second;   // alphabetical order
        }
    }

    bool ok = input && W && bias && beta && perm && hxr && hxi;

    if (!ok && n_in == 7) {
        W     = (const float*)d_in[0];
        bias  = (const float*)d_in[1];
        beta  = (const float*)d_in[2];
        hxi   = (const float*)d_in[3];
        hxr   = (const float*)d_in[4];
        input = (const float*)d_in[5];
        perm  = (const int*)d_in[6];
        aLim  = (long long)in_sizes[5] < aLim  ? (long long)in_sizes[5] : aLim;
        wLim  = (long long)in_sizes[0] < wLim  ? (long long)in_sizes[0] : wLim;
        bLim  = (long long)in_sizes[1] < bLim  ? (long long)in_sizes[1] : bLim;
        long long h3 = (long long)in_sizes[3], h4 = (long long)in_sizes[4];
        long long hmin = h3 < h4 ? h3 : h4;
        hxLim = hmin < hxLim ? hmin : hxLim;
        ok = true;
    }

    long long outCap = (long long)out_size;

    if (!ok) {
        long long n = outCap;
        if (n > 0)
            zero_out_kernel<<<(unsigned)((n + 255) / 256), 256>>>((float*)d_out, n);
        return;
    }

    // Resolve device-global scratch pointers (host side, graph-safe).
    __nv_bfloat16 *pAhi, *pAlo, *pWhi, *pWlo;
    cudaGetSymbolAddress((void**)&pAhi, g_Ahi);
    cudaGetSymbolAddress((void**)&pAlo, g_Alo);
    cudaGetSymbolAddress((void**)&pWhi, g_Whi);
    cudaGetSymbolAddress((void**)&pWlo, g_Wlo);

    // Pre-split A and W into bf16 hi/lo
    long long nA = (long long)BATCH * INPUT_D;
    long long nW = (long long)FIVEH * INPUT_D;
    split_kernel<<<(unsigned)(nA / 4 / 256), 256>>>(
        input, pAhi, pAlo, nA, (aLim & ~3LL) - 4);
    split_kernel<<<(unsigned)(nW / 4 / 256), 256>>>(
        W, pWhi, pWlo, nW, (wLim & ~3LL) - 4);

    dim3 g1(FIVEH / BN, BATCH / BM);   // (80, 16)
    gemm_kernel<<<g1, 256>>>(pAhi, pAlo, pWhi, pWlo, bias, bLim - 1);

    fused_kernel<<<BATCH, 256>>>(hxr, hxi, perm, beta, (float*)d_out,
                                 hxLim, outCap);
}

// round 17
// speedup vs baseline: 1.5979x; 1.0040x over previous
#include <cuda_runtime.h>
#include <cuda_bf16.h>
#include <math.h>

#define HIDDEN 2048
#define INPUT_D 128
#define BATCH 2048
#define FIVEH (5 * HIDDEN)

// Scratch for up = input @ W^T + b  (2048 x 10240 f32 = 84MB)
__device__ __align__(16) float g_up[(size_t)BATCH * FIVEH];

// Pre-split bf16 operands (hi + lo residual)
__device__ __align__(16) __nv_bfloat16 g_Ahi[(size_t)BATCH * INPUT_D];
__device__ __align__(16) __nv_bfloat16 g_Alo[(size_t)BATCH * INPUT_D];
__device__ __align__(16) __nv_bfloat16 g_Whi[(size_t)FIVEH * INPUT_D];
__device__ __align__(16) __nv_bfloat16 g_Wlo[(size_t)FIVEH * INPUT_D];

__device__ __forceinline__ long long ll_min2(long long a, long long b) {
    return a < b ? a : b;
}

// ============================================================================
// Split kernel: f32 -> bf16 hi + bf16 lo (residual), vectorized x4.
// ============================================================================
__global__ void split_kernel(const float* __restrict__ src,
                             __nv_bfloat16* __restrict__ hi,
                             __nv_bfloat16* __restrict__ lo,
                             long long n, long long srcLast4)
{
    long long i = 4LL * ((long long)blockIdx.x * blockDim.x + threadIdx.x);
    if (i >= n) return;
    long long off = ll_min2(i, srcLast4);
    float4 v = *(const float4*)(src + off);
    float a[4] = {v.x, v.y, v.z, v.w};
    __nv_bfloat16 h[4], l[4];
#pragma unroll
    for (int e = 0; e < 4; e++) {
        h[e] = __float2bfloat16(a[e]);
        l[e] = __float2bfloat16(a[e] - __bfloat162float(h[e]));
    }
    *(__nv_bfloat162*)&hi[i]     = make_bfloat162(h[0], h[1]);
    *(__nv_bfloat162*)&hi[i + 2] = make_bfloat162(h[2], h[3]);
    *(__nv_bfloat162*)&lo[i]     = make_bfloat162(l[0], l[1]);
    *(__nv_bfloat162*)&lo[i + 2] = make_bfloat162(l[2], l[3]);
}

// ============================================================================
// Kernel 1: GEMM via tensor cores (mma m16n8k16 bf16, pre-split 3-term)
//   C = Ah*Wh + Ah*Wl + Al*Wh  (+bias). ldmatrix fragment loads.
// ============================================================================
#define BM 128
#define BN 128
#define KT 32
#define SROW 40            // bf16 elems per smem row (80B; LDSM conflict-free)

__device__ __forceinline__ void mma16816(
    float& c0, float& c1, float& c2, float& c3,
    unsigned a0, unsigned a1, unsigned a2, unsigned a3,
    unsigned b0, unsigned b1)
{
    asm volatile(
        "mma.sync.aligned.m16n8k16.row.col.f32.bf16.bf16.f32 "
        "{%0,%1,%2,%3}, {%4,%5,%6,%7}, {%8,%9}, {%0,%1,%2,%3};"
        : "+f"(c0), "+f"(c1), "+f"(c2), "+f"(c3)
        : "r"(a0), "r"(a1), "r"(a2), "r"(a3), "r"(b0), "r"(b1));
}

__device__ __forceinline__ void ldsm_x4(unsigned& r0, unsigned& r1,
                                        unsigned& r2, unsigned& r3,
                                        const void* p)
{
    unsigned addr = (unsigned)__cvta_generic_to_shared(p);
    asm volatile("ldmatrix.sync.aligned.m8n8.x4.shared.b16 {%0,%1,%2,%3}, [%4];"
                 : "=r"(r0), "=r"(r1), "=r"(r2), "=r"(r3) : "r"(addr));
}

__global__ __launch_bounds__(256) void gemm_kernel(
    const __nv_bfloat16* __restrict__ Ahi,
    const __nv_bfloat16* __restrict__ Alo,
    const __nv_bfloat16* __restrict__ Whi,
    const __nv_bfloat16* __restrict__ Wlo,
    const float* __restrict__ bias, long long bLast)
{
    __shared__ __nv_bfloat16 As_hi[BM][SROW];
    __shared__ __nv_bfloat16 As_lo[BM][SROW];
    __shared__ __nv_bfloat16 Ws_hi[BN][SROW];
    __shared__ __nv_bfloat16 Ws_lo[BN][SROW];

    const int tid = threadIdx.x;
    const int bn = blockIdx.x * BN;
    const int bm = blockIdx.y * BM;

    const int wid = tid >> 5;
    const int lane = tid & 31;
    const int g = lane >> 2;
    const int t = lane & 3;
    const int Rm = (wid >> 1) * 32;     // 4 warp-rows of 32
    const int Cn = (wid & 1) * 64;      // 2 warp-cols of 64

    const int quad = lane >> 3;         // ldmatrix addressing
    const int ln = lane & 7;

    float acc[2][8][4];
#pragma unroll
    for (int i = 0; i < 2; i++)
#pragma unroll
        for (int j = 0; j < 8; j++)
#pragma unroll
            for (int r = 0; r < 4; r++) acc[i][j][r] = 0.0f;

    const int lrow = tid >> 1;          // fill: smem row
    const int lkc  = (tid & 1) * 16;    // fill: k col base (0/16)

    for (int kt = 0; kt < INPUT_D; kt += KT) {
        // ---- fill: pure uint4 copies of pre-split bf16 ----
        {
            size_t aoff = (size_t)(bm + lrow) * INPUT_D + kt + lkc;
            *(uint4*)&As_hi[lrow][lkc]     = *(const uint4*)(Ahi + aoff);
            *(uint4*)&As_hi[lrow][lkc + 8] = *(const uint4*)(Ahi + aoff + 8);
            *(uint4*)&As_lo[lrow][lkc]     = *(const uint4*)(Alo + aoff);
            *(uint4*)&As_lo[lrow][lkc + 8] = *(const uint4*)(Alo + aoff + 8);
            size_t woff = (size_t)(bn + lrow) * INPUT_D + kt + lkc;
            *(uint4*)&Ws_hi[lrow][lkc]     = *(const uint4*)(Whi + woff);
            *(uint4*)&Ws_hi[lrow][lkc + 8] = *(const uint4*)(Whi + woff + 8);
            *(uint4*)&Ws_lo[lrow][lkc]     = *(const uint4*)(Wlo + woff);
            *(uint4*)&Ws_lo[lrow][lkc + 8] = *(const uint4*)(Wlo + woff + 8);
        }
        __syncthreads();

#pragma unroll
        for (int s = 0; s < 2; s++) {
            const int ks0 = s * 16;

            // A fragments: rows Rm + mt*16 + {ln, +8}, k = ks0 + {0,8}
            const int arow = ln + (quad & 1) * 8;
            const int akc = ks0 + (quad >> 1) * 8;
            unsigned ah[2][4], al[2][4];
#pragma unroll
            for (int mt = 0; mt < 2; mt++) {
                int r = Rm + mt * 16 + arow;
                ldsm_x4(ah[mt][0], ah[mt][1], ah[mt][2], ah[mt][3],
                        &As_hi[r][akc]);
                ldsm_x4(al[mt][0], al[mt][1], al[mt][2], al[mt][3],
                        &As_lo[r][akc]);
            }

            // B fragments: 16 n-rows per LDSM.x4
            const int brow = ln + (quad >> 1) * 8;
            const int bkc = ks0 + (quad & 1) * 8;
            unsigned bh[8][2], bl[8][2];
#pragma unroll
            for (int ntp = 0; ntp < 4; ntp++) {
                int c = Cn + ntp * 16 + brow;
                ldsm_x4(bh[2 * ntp][0], bh[2 * ntp][1],
                        bh[2 * ntp + 1][0], bh[2 * ntp + 1][1],
                        &Ws_hi[c][bkc]);
                ldsm_x4(bl[2 * ntp][0], bl[2 * ntp][1],
                        bl[2 * ntp + 1][0], bl[2 * ntp + 1][1],
                        &Ws_lo[c][bkc]);
            }

#pragma unroll
            for (int mt = 0; mt < 2; mt++)
#pragma unroll
                for (int nt = 0; nt < 8; nt++) {
                    float* cc = acc[mt][nt];
                    mma16816(cc[0], cc[1], cc[2], cc[3],
                             ah[mt][0], ah[mt][1], ah[mt][2], ah[mt][3],
                             bh[nt][0], bh[nt][1]);
                    mma16816(cc[0], cc[1], cc[2], cc[3],
                             ah[mt][0], ah[mt][1], ah[mt][2], ah[mt][3],
                             bl[nt][0], bl[nt][1]);
                    mma16816(cc[0], cc[1], cc[2], cc[3],
                             al[mt][0], al[mt][1], al[mt][2], al[mt][3],
                             bh[nt][0], bh[nt][1]);
                }
        }
        __syncthreads();
    }

    // ---- epilogue: add bias, write f32 ----
#pragma unroll
    for (int nt = 0; nt < 8; nt++) {
        long long col = bn + Cn + nt * 8 + 2 * t;
        float b0 = bias[ll_min2(col, bLast)];
        float b1 = bias[ll_min2(col + 1, bLast)];
#pragma unroll
        for (int mt = 0; mt < 2; mt++) {
            int row = bm + Rm + mt * 16 + g;
            float* cc = acc[mt][nt];
            *(float2*)(g_up + (size_t)row * FIVEH + col) =
                make_float2(cc[0] + b0, cc[1] + b1);
            *(float2*)(g_up + (size_t)(row + 8) * FIVEH + col) =
                make_float2(cc[2] + b0, cc[3] + b1);
        }
    }
}

// ============================================================================
// Kernel 2: fused URNN core (FROZEN from round 14). One block per batch row.
// ============================================================================

__device__ __forceinline__ float2 cmul(float2 a, float2 b) {
    return make_float2(a.x * b.x - a.y * b.y, a.x * b.y + a.y * b.x);
}

template <int SIGN>
__device__ float2* fft2048(float2* __restrict__ a, float2* __restrict__ b, int tid)
{
    float2* src = a;
    float2* dst = b;
    const float TW = SIGN * 0.0030679615757712823f;   // SIGN * 2*pi / 2048
    int m = 1;

#pragma unroll 1
    for (int st = 0; st < 5; st++) {
#pragma unroll
        for (int q = 0; q < 2; q++) {
            int t = tid + q * 256;
            int k = t & (m - 1);
            float2 c0 = src[t];
            float2 c1 = src[t + 512];
            float2 c2 = src[t + 1024];
            float2 c3 = src[t + 1536];
            float2 s02 = make_float2(c0.x + c2.x, c0.y + c2.y);
            float2 d02 = make_float2(c0.x - c2.x, c0.y - c2.y);
            float2 s13 = make_float2(c1.x + c3.x, c1.y + c3.y);
            float2 d13 = make_float2(c1.x - c3.x, c1.y - c3.y);
            float2 jd13 = (SIGN < 0) ? make_float2(d13.y, -d13.x)
                                     : make_float2(-d13.y, d13.x);
            float2 y0 = make_float2(s02.x + s13.x, s02.y + s13.y);
            float2 y2 = make_float2(s02.x - s13.x, s02.y - s13.y);
            float2 y1 = make_float2(d02.x + jd13.x, d02.y + jd13.y);
            float2 y3 = make_float2(d02.x - jd13.x, d02.y - jd13.y);

            float ang = (float)(t - k) * TW;
            float sw, cw;
            __sincosf(ang, &sw, &cw);
            float2 w1 = make_float2(cw, sw);
            float2 w2 = make_float2(cw * cw - sw * sw, 2.0f * cw * sw);
            float2 w3 = cmul(w2, w1);

            int d0 = (t << 2) - 3 * k;
            dst[d0]         = y0;
            dst[d0 + m]     = cmul(y1, w1);
            dst[d0 + 2 * m] = cmul(y2, w2);
            dst[d0 + 3 * m] = cmul(y3, w3);
        }
        __syncthreads();
        float2* tmp = src; src = dst; dst = tmp;
        m <<= 2;
    }

#pragma unroll
    for (int q = 0; q < 4; q++) {
        int t = tid + q * 256;
        float2 c0 = src[t];
        float2 c1 = src[t + 1024];
        dst[t]        = make_float2(c0.x + c1.x, c0.y + c1.y);
        dst[t + 1024] = make_float2(c0.x - c1.x, c0.y - c1.y);
    }
    __syncthreads();
    return dst;
}

__device__ __forceinline__ float2 block_reduce_c2(float2 v, float2* red)
{
#pragma unroll
    for (int off = 16; off > 0; off >>= 1) {
        v.x += __shfl_xor_sync(0xFFFFFFFFu, v.x, off);
        v.y += __shfl_xor_sync(0xFFFFFFFFu, v.y, off);
    }
    __syncthreads();
    int lane = threadIdx.x & 31;
    int w = threadIdx.x >> 5;
    if (lane == 0) red[w] = v;
    __syncthreads();
    float2 sum = make_float2(0.f, 0.f);
#pragma unroll
    for (int i = 0; i < 8; i++) { sum.x += red[i].x; sum.y += red[i].y; }
    return sum;
}

__global__ __launch_bounds__(256) void fused_kernel(
    const float* __restrict__ hxr,
    const float* __restrict__ hxi,
    const int*   __restrict__ perm,
    const float* __restrict__ beta,
    float*       __restrict__ out,
    long long hxLim,
    long long outCap)
{
    __shared__ float2 bufA[HIDDEN];
    __shared__ float2 bufB[HIDDEN];
    __shared__ float2 red[8];

    const int b = blockIdx.x;
    const int tid = threadIdx.x;
    const float* uprow = g_up + (size_t)b * FIVEH;
    const size_t rowoff = (size_t)b * HIDDEN;
    const long long hxLast = hxLim - 1;

#pragma unroll
    for (int q = 0; q < 8; q++) {
        int i = tid + q * 256;
        float sp, cp;
        __sincosf(uprow[i], &sp, &cp);                 // d1 = (cp, sp)
        long long hidx = ll_min2((long long)(rowoff + i), hxLast);
        float xr = hxr[hidx];
        float xi = hxi[hidx];
        bufA[i] = make_float2(cp * xr - sp * xi, cp * xi + sp * xr);
    }
    __syncthreads();

    float2* h = fft2048<-1>(bufA, bufB, tid);

    float2 rc[8];
    float2 acc = make_float2(0.f, 0.f);
#pragma unroll
    for (int q = 0; q < 8; q++) {
        int i = tid + q * 256;
        float sp, cp;
        __sincosf(uprow[3 * HIDDEN + i], &sp, &cp);
        rc[q] = make_float2(cp, sp);
        float2 hv = h[i];
        acc.x += cp * hv.x + sp * hv.y;
        acc.y += cp * hv.y - sp * hv.x;
    }
    float2 proj = block_reduce_c2(acc, red);
#pragma unroll
    for (int q = 0; q < 8; q++) {
        int i = tid + q * 256;
        float2 rp = cmul(rc[q], proj);
        float2 hv = h[i];
        h[i] = make_float2(hv.x - 2.f * rp.x, hv.y - 2.f * rp.y);
    }
    __syncthreads();

    float2* g = (h == bufA) ? bufB : bufA;
#pragma unroll
    for (int q = 0; q < 8; q++) {
        int i = tid + q * 256;
        float sp, cp;
        __sincosf(uprow[HIDDEN + i], &sp, &cp);        // d2
        float2 hv = h[perm[i] & (HIDDEN - 1)];
        g[i] = make_float2(cp * hv.x - sp * hv.y, cp * hv.y + sp * hv.x);
    }
    __syncthreads();

    float2* h2 = fft2048<1>(g, h, tid);

    acc = make_float2(0.f, 0.f);
#pragma unroll
    for (int q = 0; q < 8; q++) {
        int i = tid + q * 256;
        float sp, cp;
        __sincosf(uprow[4 * HIDDEN + i], &sp, &cp);
        rc[q] = make_float2(cp, sp);
        float2 hv = h2[i];
        acc.x += cp * hv.x + sp * hv.y;
        acc.y += cp * hv.y - sp * hv.x;
    }
    float2 proj2 = block_reduce_c2(acc, red);

    const float inv = 1.0f / (float)HIDDEN;
#pragma unroll
    for (int q = 0; q < 8; q++) {
        int i = tid + q * 256;
        float2 rp = cmul(rc[q], proj2);
        float2 hv = h2[i];
        float2 v = make_float2(hv.x - 2.f * rp.x, hv.y - 2.f * rp.y);
        float sp, cp;
        __sincosf(uprow[2 * HIDDEN + i], &sp, &cp);
        float2 w = make_float2((cp * v.x - sp * v.y) * inv,
                               (cp * v.y + sp * v.x) * inv);
        float mag = sqrtf(w.x * w.x + w.y * w.y);
        float nm = fmaxf(mag + beta[i], 0.0f);
        float2 o;
        if (mag > 0.0f) {
            float sc = nm / mag;
            o = make_float2(w.x * sc, w.y * sc);
        } else {
            o = make_float2(nm, 0.0f);
        }

        long long fidx = (long long)(rowoff + i);
        if (outCap >= 2LL * BATCH * HIDDEN) {
            *(float2*)(out + 2 * fidx) = o;     // full complex view
        } else if (fidx < outCap) {
            out[fidx] = o.x;                    // real part (astype f32)
        }
    }
}

__global__ void zero_out_kernel(float* out, long long n)
{
    long long i = (long long)blockIdx.x * blockDim.x + threadIdx.x;
    if (i < n) out[i] = 0.0f;
}

// ============================================================================
// Host: bind inputs BY SIZE (element or byte counts); alphabetical fallback.
// ============================================================================
static inline bool sz_match(long long s, long long elems) {
    return s == elems || s == elems * 4;
}

extern "C" void kernel_launch(void* const* d_in, const int* in_sizes, int n_in,
                              void* d_out, int out_size)
{
    const float* input = nullptr;
    const float* W     = nullptr;
    const float* bias  = nullptr;
    const float* beta  = nullptr;
    const int*   perm  = nullptr;
    const float* hx_first = nullptr;
    const float* hx_second = nullptr;

    long long aLim = (long long)BATCH * INPUT_D;
    long long wLim = (long long)FIVEH * INPUT_D;
    long long bLim = FIVEH;
    long long hxLim = (long long)BATCH * HIDDEN;

    int idx_input = -1, idx_hx_first = -1;

    for (int i = 0; i < n_in; i++) {
        long long s = (long long)in_sizes[i];
        if (sz_match(s, (long long)BATCH * INPUT_D)) {
            input = (const float*)d_in[i]; idx_input = i;
        } else if (sz_match(s, (long long)FIVEH * INPUT_D)) {
            W = (const float*)d_in[i];
        } else if (sz_match(s, (long long)FIVEH)) {
            bias = (const float*)d_in[i];
        } else if (sz_match(s, (long long)BATCH * HIDDEN)) {
            if (!hx_first) { hx_first = (const float*)d_in[i]; idx_hx_first = i; }
            else           { hx_second = (const float*)d_in[i]; }
        } else if (sz_match(s, (long long)HIDDEN)) {
            if (!beta) beta = (const float*)d_in[i];
            else       perm = (const int*)d_in[i];
        }
    }

    const float* hxr = nullptr;
    const float* hxi = nullptr;
    if (hx_first && hx_second) {
        if (idx_input >= 0 && idx_input < idx_hx_first) {
            hxr = hx_first;  hxi = hx_second;   // declared dict order
        } else {
            hxi = hx_first;  hxr = hx_second;   // alphabetical order
        }
    }

    bool ok = input && W && bias && beta && perm && hxr && hxi;

    if (!ok && n_in == 7) {
        W     = (const float*)d_in[0];
        bias  = (const float*)d_in[1];
        beta  = (const float*)d_in[2];
        hxi   = (const float*)d_in[3];
        hxr   = (const float*)d_in[4];
        input = (const float*)d_in[5];
        perm  = (const int*)d_in[6];
        aLim  = (long long)in_sizes[5] < aLim  ? (long long)in_sizes[5] : aLim;
        wLim  = (long long)in_sizes[0] < wLim  ? (long long)in_sizes[0] : wLim;
        bLim  = (long long)in_sizes[1] < bLim  ? (long long)in_sizes[1] : bLim;
        long long h3 = (long long)in_sizes[3], h4 = (long long)in_sizes[4];
        long long hmin = h3 < h4 ? h3 : h4;
        hxLim = hmin < hxLim ? hmin : hxLim;
        ok = true;
    }

    long long outCap = (long long)out_size;

    if (!ok) {
        long long n = outCap;
        if (n > 0)
            zero_out_kernel<<<(unsigned)((n + 255) / 256), 256>>>((float*)d_out, n);
        return;
    }

    // Resolve device-global scratch pointers (host side, graph-safe).
    __nv_bfloat16 *pAhi, *pAlo, *pWhi, *pWlo;
    cudaGetSymbolAddress((void**)&pAhi, g_Ahi);
    cudaGetSymbolAddress((void**)&pAlo, g_Alo);
    cudaGetSymbolAddress((void**)&pWhi, g_Whi);
    cudaGetSymbolAddress((void**)&pWlo, g_Wlo);

    // Pre-split A and W into bf16 hi/lo
    long long nA = (long long)BATCH * INPUT_D;
    long long nW = (long long)FIVEH * INPUT_D;
    split_kernel<<<(unsigned)(nA / 4 / 256), 256>>>(
        input, pAhi, pAlo, nA, (aLim & ~3LL) - 4);
    split_kernel<<<(unsigned)(nW / 4 / 256), 256>>>(
        W, pWhi, pWlo, nW, (wLim & ~3LL) - 4);

    dim3 g1(FIVEH / BN, BATCH / BM);   // (80, 16)
    gemm_kernel<<<g1, 256>>>(pAhi, pAlo, pWhi, pWlo, bias, bLim - 1);

    fused_kernel<<<BATCH, 256>>>(hxr, hxi, perm, beta, (float*)d_out,
                                 hxLim, outCap);
}